// round 15
// baseline (speedup 1.0000x reference)
#include <cuda_runtime.h>
#include <cuda_bf16.h>
#include <math.h>
#include <stdint.h>

#define BB 8
#define SS 256
#define HH 100
#define PP 20
#define NP 21
#define EPSF 1e-8f
#define NTOK (BB*SS)
#define OD 105
#define NEGINF -3.0e38f

__device__ float g_cp[NTOK*HH], g_ch[NTOK*HH];
__device__ float g_np[NTOK], g_nh[NTOK];
__device__ float g_wn[2][4][NTOK*PP];
__device__ int   g_len[2][BB];
__device__ float g_last[2][BB*HH];
__device__ float g_cos[BB*SS*SS];
__device__ float g_psum[2][BB*NP*SS], g_pmax[2][BB*NP*SS];
__device__ float g_hsum[2][BB*NP*SS], g_hmax[2][BB*NP*SS];
__device__ __align__(16) uint32_t g_bsplit[BB*2][2][128*60];
__device__ __align__(16) uint32_t g_asplit[NP][BB][2][2][128*60];

__device__ __forceinline__ uint32_t smem_u32(const void* p) {
    uint32_t a;
    asm("{ .reg .u64 t; cvta.to.shared.u64 t, %1; cvt.u32.u64 %0, t; }" : "=r"(a) : "l"(p));
    return a;
}
__device__ __forceinline__ uint32_t pack_split(float v0, float v1, uint32_t& lo_out) {
    __nv_bfloat16 h0 = __float2bfloat16(v0);
    __nv_bfloat16 l0 = __float2bfloat16(v0 - __bfloat162float(h0));
    __nv_bfloat16 h1 = __float2bfloat16(v1);
    __nv_bfloat16 l1 = __float2bfloat16(v1 - __bfloat162float(h1));
    lo_out = (uint32_t)__bfloat16_as_ushort(l0) | ((uint32_t)__bfloat16_as_ushort(l1) << 16);
    return (uint32_t)__bfloat16_as_ushort(h0) | ((uint32_t)__bfloat16_as_ushort(h1) << 16);
}

#define MMA16816(c, a, bb) \
    asm volatile("mma.sync.aligned.m16n8k16.row.col.f32.bf16.bf16.f32 " \
        "{%0,%1,%2,%3}, {%4,%5,%6,%7}, {%8,%9}, {%0,%1,%2,%3};" \
        : "+f"((c)[0]), "+f"((c)[1]), "+f"((c)[2]), "+f"((c)[3]) \
        : "r"((a)[0]), "r"((a)[1]), "r"((a)[2]), "r"((a)[3]), \
          "r"((bb)[0]), "r"((bb)[1]))
#define LDSM4(r, a) \
    asm volatile("ldmatrix.sync.aligned.m8n8.x4.shared.b16 {%0,%1,%2,%3}, [%4];" \
        : "=r"((r)[0]), "=r"((r)[1]), "=r"((r)[2]), "=r"((r)[3]) : "r"(a))
#define LDSM2(r, a) \
    asm volatile("ldmatrix.sync.aligned.m8n8.x2.shared.b16 {%0,%1}, [%2];" \
        : "=r"((r)[0]), "=r"((r)[1]) : "r"(a))

// ---- K0: masked ctx, norms, weighted norms, len+last; side1 emits split B tiles --
__global__ void __launch_bounds__(256) k_prep(
    const float* __restrict__ ctx_p, const int* __restrict__ mask_p,
    const float* __restrict__ ctx_h, const int* __restrict__ mask_h,
    const float* __restrict__ w_full, const float* __restrict__ w_mp,
    const float* __restrict__ w_att, const float* __restrict__ w_ma)
{
    __shared__ float tile[32][101];
    __shared__ int slen;
    int c0 = blockIdx.x * 32, b = blockIdx.y, side = blockIdx.z;
    const float* ctx = side ? ctx_h : ctx_p;
    const int* mask = side ? mask_h : mask_p;
    float* rowdst = side ? g_ch : g_cp;
    int t = threadIdx.x;
    int base = b*SS + c0;
    if (t == 0) slen = 0;

    for (int e = t; e < 32*HH; e += 256) {
        int i = e / HH, h = e - i*HH;
        float v = ctx[(base + i)*HH + h] * (float)mask[base + i];
        tile[i][h] = v;
        rowdst[(base + i)*HH + h] = v;
    }
    __syncthreads();
    atomicAdd(&slen, mask[b*SS + t]);

    int lane = t & 31, wl = t >> 5;
    for (int k = 0; k < 4; k++) {
        int i = wl*4 + k;
        float qq = 0.f;
        for (int h = lane; h < HH; h += 32) { float v = tile[i][h]; qq += v*v; }
        #pragma unroll
        for (int o = 16; o; o >>= 1) qq += __shfl_xor_sync(0xffffffffu, qq, o);
        if (lane == 0) (side ? g_nh : g_np)[base + i] = sqrtf(qq);
    }

    const float* ws[4] = {w_full, w_mp, w_att, w_ma};
    for (int it = 0; it < 10; it++) {
        int task = t + 256*it;
        int wp = task >> 5, i = task & 31;
        int w = wp / PP, p = wp - w*PP;
        const float* wr = ws[w] + p*HH;
        float s = 0.f;
        #pragma unroll 4
        for (int h = 0; h < HH; h++) { float ww = wr[h]; float v = tile[i][h]; s += ww*ww*v*v; }
        g_wn[side][w][(base + i)*PP + p] = sqrtf(s);
    }

    if (side == 1) {
        int half = c0 >> 7, r0 = c0 & 127;
        uint32_t* hiB = &g_bsplit[b*2 + half][0][0];
        uint32_t* loB = &g_bsplit[b*2 + half][1][0];
        for (int e = t; e < 32*60; e += 256) {
            int i = e / 60, c2 = e - (e/60)*60;
            float v0 = (2*c2 < HH) ? tile[i][2*c2] : 0.f;
            float v1 = (2*c2+1 < HH) ? tile[i][2*c2+1] : 0.f;
            uint32_t lo, hi = pack_split(v0, v1, lo);
            int wdx = (r0 + i)*60 + c2;
            hiB[wdx] = hi; loB[wdx] = lo;
        }
    }

    __syncthreads();
    int len = slen;
    int last = len > 0 ? len - 1 : 0;
    if (c0 == 0 && t == 0) g_len[side][b] = len;
    if (last >= c0 && last < c0 + 32)
        for (int h = t; h < HH; h += 256)
            g_last[side][b*HH + h] = tile[last - c0][h];
}

// ---- K0c: pre-scale + split A tiles for all 21 perspectives ----------------------
__global__ void __launch_bounds__(256) k_splitA(const float* __restrict__ w_mp)
{
    int ih = blockIdx.x, p = blockIdx.y, b = blockIdx.z;
    __shared__ float w2s[128];
    int t = threadIdx.x;
    if (t < 128)
        w2s[t] = (t < HH) ? ((p < PP) ? w_mp[p*HH + t]*w_mp[p*HH + t] : 1.0f) : 0.f;
    __syncthreads();
    const float* cpb = g_cp + (size_t)(b*SS + ih*128)*HH;
    uint32_t* hiA = &g_asplit[p][b][ih][0][0];
    uint32_t* loA = &g_asplit[p][b][ih][1][0];
    for (int e = t; e < 7680; e += 256) {
        int row = e / 60, c2 = e - row*60;
        const float* sr = cpb + row*HH;
        float v0 = (2*c2 < HH) ? w2s[2*c2]*sr[2*c2] : 0.f;
        float v1 = (2*c2+1 < HH) ? w2s[2*c2+1]*sr[2*c2+1] : 0.f;
        uint32_t lo, hi = pack_split(v0, v1, lo);
        hiA[e] = hi; loA[e] = lo;
    }
}

// ---- K1: mma.sync split-bf16 GEMM, 3-stage smem, ldmatrix fragment loads ---------
#define SMEM_DYN ((2*7680 + 1536)*4)
__global__ void __launch_bounds__(256, 2) k_mma()
{
    extern __shared__ __align__(16) uint32_t dsm[];
    uint32_t* AW = dsm;
    uint32_t* BW = dsm + 7680;
    float* sjred = (float*)(dsm + 2*7680);
    float* mjred = sjred + 512;
    float* sired = mjred + 512;
    float* mired = sired + 256;
    __shared__ float inv1s[128], inv2s[128];

    int ih = blockIdx.x >> 1, jh = blockIdx.x & 1;
    int p = blockIdx.y, b = blockIdx.z;
    int t = threadIdx.x;
    int w = t >> 5, lane = t & 31;
    int g = lane >> 2, q = lane & 3;
    int wi = w >> 2, wj = w & 3;

    if (t < 128) {
        int gi = b*SS + ih*128 + t;
        float n1 = (p < PP) ? g_wn[0][1][gi*PP + p] : g_np[gi];
        inv1s[t] = 1.0f / fmaxf(n1, (p < PP) ? 1e-4f : EPSF);
        int gj = b*SS + jh*128 + t;
        float n2 = (p < PP) ? g_wn[1][1][gj*PP + p] : g_nh[gj];
        inv2s[t] = 1.0f / fmaxf(n2, (p < PP) ? 1e-4f : EPSF);
    }

    uint32_t aw0 = smem_u32(AW), bw0 = smem_u32(BW);
    uint32_t aAdr[4], bAdr[4];
    #pragma unroll
    for (int m = 0; m < 4; m++)
        aAdr[m] = aw0 + ((((wi*64 + m*16 + (lane & 15))*60) + (lane >> 4)*4) << 2);
    #pragma unroll
    for (int n = 0; n < 4; n++)
        bAdr[n] = bw0 + ((((wj*32 + n*8 + (lane & 7))*60) + ((lane >> 3) & 1)*4) << 2);

    const float4* aHi = (const float4*)&g_asplit[p][b][ih][0][0];
    const float4* aLo = (const float4*)&g_asplit[p][b][ih][1][0];
    const float4* bHi = (const float4*)&g_bsplit[b*2 + jh][0][0];
    const float4* bLo = (const float4*)&g_bsplit[b*2 + jh][1][0];
    float4* dA = (float4*)AW;
    float4* dB = (float4*)BW;

    float acc[4][4][4];
    #pragma unroll
    for (int m = 0; m < 4; m++)
        #pragma unroll
        for (int n = 0; n < 4; n++)
            #pragma unroll
            for (int k = 0; k < 4; k++) acc[m][n][k] = 0.f;

    #define MMA_PASS() do { \
        _Pragma("unroll") \
        for (int ks = 0; ks < 7; ks++) { \
            uint32_t aF[4][4], bF[4][2]; \
            _Pragma("unroll") \
            for (int m = 0; m < 4; m++) LDSM4(aF[m], aAdr[m] + ks*32); \
            _Pragma("unroll") \
            for (int n = 0; n < 4; n++) LDSM2(bF[n], bAdr[n] + ks*32); \
            _Pragma("unroll") \
            for (int m = 0; m < 4; m++) \
                _Pragma("unroll") \
                for (int n = 0; n < 4; n++) \
                    MMA16816(acc[m][n], aF[m], bF[n]); \
        } \
    } while (0)

    #pragma unroll
    for (int e = t; e < 1920; e += 256) { dA[e] = aHi[e]; dB[e] = bLo[e]; }
    __syncthreads();
    MMA_PASS();
    __syncthreads();
    #pragma unroll
    for (int e = t; e < 1920; e += 256) dB[e] = bHi[e];
    __syncthreads();
    MMA_PASS();
    __syncthreads();
    #pragma unroll
    for (int e = t; e < 1920; e += 256) dA[e] = aLo[e];
    __syncthreads();
    MMA_PASS();

    int lh = g_len[1][b], lp = g_len[0][b];
    int lhl = min(max(lh - jh*128, 0), 128);
    int lpl = min(max(lp - ih*128, 0), 128);

    float i1a[4], i1b[4], i2a[4], i2b[4];
    #pragma unroll
    for (int m = 0; m < 4; m++) {
        i1a[m] = inv1s[wi*64 + m*16 + g];
        i1b[m] = inv1s[wi*64 + m*16 + g + 8];
    }
    #pragma unroll
    for (int n = 0; n < 4; n++) {
        i2a[n] = inv2s[wj*32 + n*8 + 2*q];
        i2b[n] = inv2s[wj*32 + n*8 + 2*q + 1];
    }

    float jsum[8], jmaxv[8], isum[8], imaxv[8];
    #pragma unroll
    for (int k = 0; k < 8; k++) { jsum[k] = 0.f; jmaxv[k] = NEGINF; isum[k] = 0.f; imaxv[k] = NEGINF; }

    #pragma unroll
    for (int m = 0; m < 4; m++) {
        int r0v = wi*64 + m*16 + g;
        bool rv0 = r0v < lpl, rv1 = (r0v + 8) < lpl;
        #pragma unroll
        for (int n = 0; n < 4; n++) {
            int c0 = wj*32 + n*8 + 2*q;
            bool cv0 = c0 < lhl, cv1 = (c0 + 1) < lhl;
            float v0 = acc[m][n][0]*i1a[m]*i2a[n];
            float v1 = acc[m][n][1]*i1a[m]*i2b[n];
            float v2 = acc[m][n][2]*i1b[m]*i2a[n];
            float v3 = acc[m][n][3]*i1b[m]*i2b[n];
            jsum[2*m] += v0 + v1;  jsum[2*m+1] += v2 + v3;
            if (cv0) { jmaxv[2*m] = fmaxf(jmaxv[2*m], v0); jmaxv[2*m+1] = fmaxf(jmaxv[2*m+1], v2); }
            if (cv1) { jmaxv[2*m] = fmaxf(jmaxv[2*m], v1); jmaxv[2*m+1] = fmaxf(jmaxv[2*m+1], v3); }
            isum[2*n] += v0 + v2;  isum[2*n+1] += v1 + v3;
            if (rv0) { imaxv[2*n] = fmaxf(imaxv[2*n], v0); imaxv[2*n+1] = fmaxf(imaxv[2*n+1], v1); }
            if (rv1) { imaxv[2*n] = fmaxf(imaxv[2*n], v2); imaxv[2*n+1] = fmaxf(imaxv[2*n+1], v3); }
            if (p == PP) {
                float* dst = g_cos + (size_t)(b*SS + ih*128 + r0v)*SS + jh*128 + c0;
                float2 s0; s0.x = v0; s0.y = v1;
                float2 s1; s1.x = v2; s1.y = v3;
                *(float2*)dst = s0;
                *(float2*)(dst + 8*SS) = s1;
            }
        }
    }

    #pragma unroll
    for (int k = 0; k < 8; k++) {
        #pragma unroll
        for (int off = 1; off <= 2; off <<= 1) {
            jsum[k] += __shfl_xor_sync(0xffffffffu, jsum[k], off);
            jmaxv[k] = fmaxf(jmaxv[k], __shfl_xor_sync(0xffffffffu, jmaxv[k], off));
        }
        #pragma unroll
        for (int off = 4; off <= 16; off <<= 1) {
            isum[k] += __shfl_xor_sync(0xffffffffu, isum[k], off);
            imaxv[k] = fmaxf(imaxv[k], __shfl_xor_sync(0xffffffffu, imaxv[k], off));
        }
    }
    if (q == 0) {
        #pragma unroll
        for (int m = 0; m < 4; m++) {
            #pragma unroll
            for (int hf = 0; hf < 2; hf++) {
                int row = wi*64 + m*16 + hf*8 + g;
                sjred[wj*128 + row] = jsum[2*m + hf];
                mjred[wj*128 + row] = jmaxv[2*m + hf];
            }
        }
    }
    if (g == 0) {
        #pragma unroll
        for (int n = 0; n < 4; n++) {
            int c0 = wj*32 + n*8 + 2*q;
            sired[wi*128 + c0] = isum[2*n];     sired[wi*128 + c0 + 1] = isum[2*n+1];
            mired[wi*128 + c0] = imaxv[2*n];    mired[wi*128 + c0 + 1] = imaxv[2*n+1];
        }
    }
    __syncthreads();
    if (t < 128) {
        float s = sjred[t] + sjred[128 + t] + sjred[256 + t] + sjred[384 + t];
        float m = fmaxf(fmaxf(mjred[t], mjred[128 + t]), fmaxf(mjred[256 + t], mjred[384 + t]));
        int idx = (b*NP + p)*SS + ih*128 + t;
        g_psum[jh][idx] = s;
        g_pmax[jh][idx] = m;
        float s2 = sired[t] + sired[128 + t];
        float m2 = fmaxf(mired[t], mired[128 + t]);
        int idx2 = (b*NP + p)*SS + jh*128 + t;
        g_hsum[ih][idx2] = s2;
        g_hmax[ih][idx2] = m2;
    }
}

// ---- K3: comb + attentive mean/max + all matchings. 4 tokens/block, 1024 blocks --
__global__ void __launch_bounds__(256) k_att(const float* __restrict__ w_att,
                                             const float* __restrict__ w_ma,
                                             const float* __restrict__ w_full,
                                             float* __restrict__ out)
{
    __shared__ __align__(16) float buf1[6060];  // cst[SS][4] then wsqc3[3][20][101]
    __shared__ float buf2[1664];                // red_s[2][4][104]+red_m | prod1/2[8][104]
    __shared__ float amean[4][104], amax[4][104], lastv[104], rsum[4];
    int b = blockIdx.x, tl = blockIdx.y, side = blockIdx.z;
    int t = threadIdx.x;
    int dlen = side ? g_len[0][b] : g_len[1][b];
    float (*cst)[4] = (float(*)[4])buf1;

    // --- comb (4 tokens x 21 p) ---
    if (t < 84) {
        int il = t / 21, p = t - (t/21)*21;
        int tk = tl*4 + il;
        int idx = (b*NP + p)*SS + tk;
        float sm, mx;
        if (side == 0) {
            sm = g_psum[0][idx] + g_psum[1][idx];
            mx = fmaxf(g_pmax[0][idx], g_pmax[1][idx]);
        } else {
            sm = g_hsum[0][idx] + g_hsum[1][idx];
            mx = fmaxf(g_hmax[0][idx], g_hmax[1][idx]);
        }
        float* oo = out + ((size_t)side*NTOK + b*SS + tk)*OD;
        if (p < PP) { oo[23 + p] = mx; oo[43 + p] = sm / (float)dlen; }
        else        { oo[0] = mx;      oo[1] = sm / (float)dlen; rsum[il] = sm; }
    }
    if (t < 104) lastv[t] = (t < HH) ? g_last[side ^ 1][b*HH + t] : 0.f;

    // --- cos tile load (transposed: cst[reduce_idx][il]) ---
    if (side == 0) {
        for (int e = t; e < 4*SS; e += 256) {
            int il = e >> 8, j = e & 255;
            cst[j][il] = g_cos[(b*SS + tl*4 + il)*SS + j];
        }
    } else {
        for (int e = t; e < 4*SS; e += 256) {
            int il = e & 3, i = e >> 2;
            cst[i][il] = g_cos[(b*SS + i)*SS + tl*4 + il];
        }
    }
    __syncthreads();

    // --- attentive mean + max over reduce dim (packed f32x2 mul/add) ---
    int g2 = t >> 7, h = t & 127;
    const float* vec = side ? g_cp : g_ch;
    int jbeg = g2*128, jend = min(dlen, jbeg + 128);
    if (h < HH) {
        unsigned long long s01 = 0ull, s23 = 0ull;
        float mx0 = NEGINF, mx1 = NEGINF, mx2 = NEGINF, mx3 = NEGINF;
        for (int j = jbeg; j < jend; j++) {
            float c = __ldg(&vec[(b*SS + j)*HH + h]);
            unsigned long long cc, f01, f23;
            asm("mov.b64 %0, {%1, %1};" : "=l"(cc) : "r"(__float_as_uint(c)));
            ulonglong2 cv = *(const ulonglong2*)&cst[j][0];
            asm("mul.rn.f32x2 %0, %1, %2;" : "=l"(f01) : "l"(cv.x), "l"(cc));
            asm("mul.rn.f32x2 %0, %1, %2;" : "=l"(f23) : "l"(cv.y), "l"(cc));
            asm("add.rn.f32x2 %0, %0, %1;" : "+l"(s01) : "l"(f01));
            asm("add.rn.f32x2 %0, %0, %1;" : "+l"(s23) : "l"(f23));
            unsigned lo, hi;
            asm("mov.b64 {%0,%1}, %2;" : "=r"(lo), "=r"(hi) : "l"(f01));
            mx0 = fmaxf(mx0, __uint_as_float(lo)); mx1 = fmaxf(mx1, __uint_as_float(hi));
            asm("mov.b64 {%0,%1}, %2;" : "=r"(lo), "=r"(hi) : "l"(f23));
            mx2 = fmaxf(mx2, __uint_as_float(lo)); mx3 = fmaxf(mx3, __uint_as_float(hi));
        }
        unsigned lo, hi;
        float* red_s = buf2;         // [2][4][104]
        float* red_m = buf2 + 832;
        asm("mov.b64 {%0,%1}, %2;" : "=r"(lo), "=r"(hi) : "l"(s01));
        red_s[(g2*4 + 0)*104 + h] = __uint_as_float(lo);
        red_s[(g2*4 + 1)*104 + h] = __uint_as_float(hi);
        asm("mov.b64 {%0,%1}, %2;" : "=r"(lo), "=r"(hi) : "l"(s23));
        red_s[(g2*4 + 2)*104 + h] = __uint_as_float(lo);
        red_s[(g2*4 + 3)*104 + h] = __uint_as_float(hi);
        red_m[(g2*4 + 0)*104 + h] = mx0;
        red_m[(g2*4 + 1)*104 + h] = mx1;
        red_m[(g2*4 + 2)*104 + h] = mx2;
        red_m[(g2*4 + 3)*104 + h] = mx3;
    }
    __syncthreads();
    if (g2 == 0 && h < HH) {
        float* red_s = buf2;
        float* red_m = buf2 + 832;
        #pragma unroll
        for (int il = 0; il < 4; il++) {
            float s = red_s[il*104 + h] + red_s[(4 + il)*104 + h];
            float m = fmaxf(red_m[il*104 + h], red_m[(4 + il)*104 + h]);
            amean[il][h] = s / fmaxf(rsum[il], EPSF);
            amax[il][h] = m;
        }
    }
    __syncthreads();

    // --- load all three w^2 tables (overwrites cst) ---
    for (int e = t; e < 6060; e += 256) {
        int which = e / 2020, r = e - which*2020;
        int p = r / 101, hh = r - p*101;
        const float* wsrc = (which == 0) ? w_att : (which == 1) ? w_ma : w_full;
        float wv = (hh < HH) ? wsrc[p*HH + hh] : 0.f;
        buf1[e] = wv*wv;
    }
    __syncthreads();

    // --- match: 12 tasks (which x token) over 8 warps ---
    int w = t >> 5, lane = t & 31;
    float* prod1 = buf2 + w*104;
    float* prod2 = buf2 + 832 + w*104;
    for (int tt = w; tt < 12; tt += 8) {
        int which = tt >> 2, il = tt & 3;
        int tok = b*SS + tl*4 + il;
        const float* v1g = (side ? g_ch : g_cp) + (size_t)tok*HH;
        float* o = out + ((size_t)side*NTOK + tok)*OD;
        const float* v2s = (which == 0) ? &amean[il][0] : (which == 1) ? &amax[il][0] : lastv;
        const float* wn1 = g_wn[side][(which == 2) ? 0 : (2 + which)];
        int col = (which == 0) ? 63 : (which == 1) ? 84 : 2;

        float r1[4], r2[4];
        float d = 0.f, q1 = 0.f, q2 = 0.f;
        #pragma unroll
        for (int k = 0; k < 4; k++) {
            int hh = k*32 + lane;
            float a = (hh < HH) ? v1g[hh] : 0.f;
            float c = (hh < HH) ? v2s[hh] : 0.f;
            r1[k] = a; r2[k] = c;
            d += a*c; q1 += a*a; q2 += c*c;
        }
        #pragma unroll
        for (int of = 16; of; of >>= 1) {
            d  += __shfl_xor_sync(0xffffffffu, d, of);
            q1 += __shfl_xor_sync(0xffffffffu, q1, of);
            q2 += __shfl_xor_sync(0xffffffffu, q2, of);
        }
        if (lane == 0)
            o[col] = d / (fmaxf(sqrtf(q1), EPSF) * fmaxf(sqrtf(q2), EPSF));

        #pragma unroll
        for (int k = 0; k < 4; k++) {
            int hh = k*32 + lane;
            if (hh < HH) { prod1[hh] = r1[k]*r2[k]; prod2[hh] = r2[k]*r2[k]; }
        }
        __syncwarp();
        if (lane < PP) {
            float s12 = 0.f, s22 = 0.f;
            const float* wr = buf1 + which*2020 + lane*101;
            #pragma unroll 4
            for (int hh = 0; hh < HH; hh++) {
                float wq = wr[hh];
                s12 += wq * prod1[hh];
                s22 += wq * prod2[hh];
            }
            float n1 = wn1[tok*PP + lane];
            o[col + 1 + lane] = s12 / (fmaxf(n1, EPSF) * fmaxf(sqrtf(s22), EPSF));
        }
        __syncwarp();
    }
}

// ---- launcher ----------------------------------------------------------------------
extern "C" void kernel_launch(void* const* d_in, const int* in_sizes, int n_in,
                              void* d_out, int out_size)
{
    const float* ctx_p  = (const float*)d_in[0];
    const int*   mask_p = (const int*)  d_in[1];
    const float* ctx_h  = (const float*)d_in[2];
    const int*   mask_h = (const int*)  d_in[3];
    const float* w_full = (const float*)d_in[4];
    const float* w_mp   = (const float*)d_in[5];
    const float* w_att  = (const float*)d_in[6];
    const float* w_ma   = (const float*)d_in[7];
    float* out = (float*)d_out;

    cudaFuncSetAttribute(k_mma, cudaFuncAttributeMaxDynamicSharedMemorySize, SMEM_DYN);

    k_prep<<<dim3(8, BB, 2), 256>>>(ctx_p, mask_p, ctx_h, mask_h, w_full, w_mp, w_att, w_ma);
    k_splitA<<<dim3(2, NP, BB), 256>>>(w_mp);
    k_mma<<<dim3(4, NP, BB), 256, SMEM_DYN>>>();
    k_att<<<dim3(BB, 64, 2), 256>>>(w_att, w_ma, w_full, out);
}

// round 16
// speedup vs baseline: 1.0707x; 1.0707x over previous
#include <cuda_runtime.h>
#include <cuda_bf16.h>
#include <math.h>
#include <stdint.h>

#define BB 8
#define SS 256
#define HH 100
#define PP 20
#define NP 21
#define EPSF 1e-8f
#define NTOK (BB*SS)
#define OD 105
#define NEGINF -3.0e38f

__device__ float g_cp[NTOK*HH], g_ch[NTOK*HH];
__device__ float g_np[NTOK], g_nh[NTOK];
__device__ float g_wn[2][4][NTOK*PP];
__device__ int   g_len[2][BB];
__device__ float g_last[2][BB*HH];
__device__ float g_cos[BB*SS*SS];
__device__ float g_psum[2][BB*NP*SS], g_pmax[2][BB*NP*SS];
__device__ float g_hsum[2][BB*NP*SS], g_hmax[2][BB*NP*SS];
__device__ __align__(16) uint32_t g_bsplit[BB*2][2][128*60];
__device__ __align__(16) uint32_t g_asplit[NP][BB][2][2][128*60];

__device__ __forceinline__ uint32_t smem_u32(const void* p) {
    uint32_t a;
    asm("{ .reg .u64 t; cvta.to.shared.u64 t, %1; cvt.u32.u64 %0, t; }" : "=r"(a) : "l"(p));
    return a;
}
__device__ __forceinline__ uint32_t pack_split(float v0, float v1, uint32_t& lo_out) {
    __nv_bfloat16 h0 = __float2bfloat16(v0);
    __nv_bfloat16 l0 = __float2bfloat16(v0 - __bfloat162float(h0));
    __nv_bfloat16 h1 = __float2bfloat16(v1);
    __nv_bfloat16 l1 = __float2bfloat16(v1 - __bfloat162float(h1));
    lo_out = (uint32_t)__bfloat16_as_ushort(l0) | ((uint32_t)__bfloat16_as_ushort(l1) << 16);
    return (uint32_t)__bfloat16_as_ushort(h0) | ((uint32_t)__bfloat16_as_ushort(h1) << 16);
}

#define MMA16816(c, a, bb) \
    asm volatile("mma.sync.aligned.m16n8k16.row.col.f32.bf16.bf16.f32 " \
        "{%0,%1,%2,%3}, {%4,%5,%6,%7}, {%8,%9}, {%0,%1,%2,%3};" \
        : "+f"((c)[0]), "+f"((c)[1]), "+f"((c)[2]), "+f"((c)[3]) \
        : "r"((a)[0]), "r"((a)[1]), "r"((a)[2]), "r"((a)[3]), \
          "r"((bb)[0]), "r"((bb)[1]))
#define LDSM4(r, a) \
    asm volatile("ldmatrix.sync.aligned.m8n8.x4.shared.b16 {%0,%1,%2,%3}, [%4];" \
        : "=r"((r)[0]), "=r"((r)[1]), "=r"((r)[2]), "=r"((r)[3]) : "r"(a))
#define LDSM2(r, a) \
    asm volatile("ldmatrix.sync.aligned.m8n8.x2.shared.b16 {%0,%1}, [%2];" \
        : "=r"((r)[0]), "=r"((r)[1]) : "r"(a))

// ---- K0: masked ctx, norms, weighted norms, len+last; side1 emits split B tiles --
__global__ void __launch_bounds__(256) k_prep(
    const float* __restrict__ ctx_p, const int* __restrict__ mask_p,
    const float* __restrict__ ctx_h, const int* __restrict__ mask_h,
    const float* __restrict__ w_full, const float* __restrict__ w_mp,
    const float* __restrict__ w_att, const float* __restrict__ w_ma)
{
    __shared__ float tile[32][101];
    __shared__ int slen;
    int c0 = blockIdx.x * 32, b = blockIdx.y, side = blockIdx.z;
    const float* ctx = side ? ctx_h : ctx_p;
    const int* mask = side ? mask_h : mask_p;
    float* rowdst = side ? g_ch : g_cp;
    int t = threadIdx.x;
    int base = b*SS + c0;
    if (t == 0) slen = 0;

    for (int e = t; e < 32*HH; e += 256) {
        int i = e / HH, h = e - i*HH;
        float v = ctx[(base + i)*HH + h] * (float)mask[base + i];
        tile[i][h] = v;
        rowdst[(base + i)*HH + h] = v;
    }
    __syncthreads();
    atomicAdd(&slen, mask[b*SS + t]);

    int lane = t & 31, wl = t >> 5;
    for (int k = 0; k < 4; k++) {
        int i = wl*4 + k;
        float qq = 0.f;
        for (int h = lane; h < HH; h += 32) { float v = tile[i][h]; qq += v*v; }
        #pragma unroll
        for (int o = 16; o; o >>= 1) qq += __shfl_xor_sync(0xffffffffu, qq, o);
        if (lane == 0) (side ? g_nh : g_np)[base + i] = sqrtf(qq);
    }

    const float* ws[4] = {w_full, w_mp, w_att, w_ma};
    for (int it = 0; it < 10; it++) {
        int task = t + 256*it;
        int wp = task >> 5, i = task & 31;
        int w = wp / PP, p = wp - w*PP;
        const float* wr = ws[w] + p*HH;
        float s = 0.f;
        #pragma unroll 4
        for (int h = 0; h < HH; h++) { float ww = wr[h]; float v = tile[i][h]; s += ww*ww*v*v; }
        g_wn[side][w][(base + i)*PP + p] = sqrtf(s);
    }

    if (side == 1) {
        int half = c0 >> 7, r0 = c0 & 127;
        uint32_t* hiB = &g_bsplit[b*2 + half][0][0];
        uint32_t* loB = &g_bsplit[b*2 + half][1][0];
        for (int e = t; e < 32*60; e += 256) {
            int i = e / 60, c2 = e - (e/60)*60;
            float v0 = (2*c2 < HH) ? tile[i][2*c2] : 0.f;
            float v1 = (2*c2+1 < HH) ? tile[i][2*c2+1] : 0.f;
            uint32_t lo, hi = pack_split(v0, v1, lo);
            int wdx = (r0 + i)*60 + c2;
            hiB[wdx] = hi; loB[wdx] = lo;
        }
    }

    __syncthreads();
    int len = slen;
    int last = len > 0 ? len - 1 : 0;
    if (c0 == 0 && t == 0) g_len[side][b] = len;
    if (last >= c0 && last < c0 + 32)
        for (int h = t; h < HH; h += 256)
            g_last[side][b*HH + h] = tile[last - c0][h];
}

// ---- K0c: pre-scale + split A tiles for all 21 perspectives ----------------------
__global__ void __launch_bounds__(256) k_splitA(const float* __restrict__ w_mp)
{
    int ih = blockIdx.x, p = blockIdx.y, b = blockIdx.z;
    __shared__ float w2s[128];
    int t = threadIdx.x;
    if (t < 128)
        w2s[t] = (t < HH) ? ((p < PP) ? w_mp[p*HH + t]*w_mp[p*HH + t] : 1.0f) : 0.f;
    __syncthreads();
    const float* cpb = g_cp + (size_t)(b*SS + ih*128)*HH;
    uint32_t* hiA = &g_asplit[p][b][ih][0][0];
    uint32_t* loA = &g_asplit[p][b][ih][1][0];
    for (int e = t; e < 7680; e += 256) {
        int row = e / 60, c2 = e - row*60;
        const float* sr = cpb + row*HH;
        float v0 = (2*c2 < HH) ? w2s[2*c2]*sr[2*c2] : 0.f;
        float v1 = (2*c2+1 < HH) ? w2s[2*c2+1]*sr[2*c2+1] : 0.f;
        uint32_t lo, hi = pack_split(v0, v1, lo);
        hiA[e] = hi; loA[e] = lo;
    }
}

// ---- K1: mma.sync split-bf16 GEMM, 3-stage smem, ldmatrix fragment loads ---------
#define SMEM_DYN ((2*7680 + 1536)*4)
__global__ void __launch_bounds__(256, 2) k_mma()
{
    extern __shared__ __align__(16) uint32_t dsm[];
    uint32_t* AW = dsm;
    uint32_t* BW = dsm + 7680;
    float* sjred = (float*)(dsm + 2*7680);
    float* mjred = sjred + 512;
    float* sired = mjred + 512;
    float* mired = sired + 256;
    __shared__ float inv1s[128], inv2s[128];

    int ih = blockIdx.x >> 1, jh = blockIdx.x & 1;
    int p = blockIdx.y, b = blockIdx.z;
    int t = threadIdx.x;
    int w = t >> 5, lane = t & 31;
    int g = lane >> 2, q = lane & 3;
    int wi = w >> 2, wj = w & 3;

    if (t < 128) {
        int gi = b*SS + ih*128 + t;
        float n1 = (p < PP) ? g_wn[0][1][gi*PP + p] : g_np[gi];
        inv1s[t] = 1.0f / fmaxf(n1, (p < PP) ? 1e-4f : EPSF);
        int gj = b*SS + jh*128 + t;
        float n2 = (p < PP) ? g_wn[1][1][gj*PP + p] : g_nh[gj];
        inv2s[t] = 1.0f / fmaxf(n2, (p < PP) ? 1e-4f : EPSF);
    }

    uint32_t aw0 = smem_u32(AW), bw0 = smem_u32(BW);
    uint32_t aAdr[4], bAdr[4];
    #pragma unroll
    for (int m = 0; m < 4; m++)
        aAdr[m] = aw0 + ((((wi*64 + m*16 + (lane & 15))*60) + (lane >> 4)*4) << 2);
    #pragma unroll
    for (int n = 0; n < 4; n++)
        bAdr[n] = bw0 + ((((wj*32 + n*8 + (lane & 7))*60) + ((lane >> 3) & 1)*4) << 2);

    const float4* aHi = (const float4*)&g_asplit[p][b][ih][0][0];
    const float4* aLo = (const float4*)&g_asplit[p][b][ih][1][0];
    const float4* bHi = (const float4*)&g_bsplit[b*2 + jh][0][0];
    const float4* bLo = (const float4*)&g_bsplit[b*2 + jh][1][0];
    float4* dA = (float4*)AW;
    float4* dB = (float4*)BW;

    float acc[4][4][4];
    #pragma unroll
    for (int m = 0; m < 4; m++)
        #pragma unroll
        for (int n = 0; n < 4; n++)
            #pragma unroll
            for (int k = 0; k < 4; k++) acc[m][n][k] = 0.f;

    #define MMA_PASS() do { \
        _Pragma("unroll") \
        for (int ks = 0; ks < 7; ks++) { \
            uint32_t aF[4][4], bF[4][2]; \
            _Pragma("unroll") \
            for (int m = 0; m < 4; m++) LDSM4(aF[m], aAdr[m] + ks*32); \
            _Pragma("unroll") \
            for (int n = 0; n < 4; n++) LDSM2(bF[n], bAdr[n] + ks*32); \
            _Pragma("unroll") \
            for (int m = 0; m < 4; m++) \
                _Pragma("unroll") \
                for (int n = 0; n < 4; n++) \
                    MMA16816(acc[m][n], aF[m], bF[n]); \
        } \
    } while (0)

    #pragma unroll
    for (int e = t; e < 1920; e += 256) { dA[e] = aHi[e]; dB[e] = bLo[e]; }
    __syncthreads();
    MMA_PASS();
    __syncthreads();
    #pragma unroll
    for (int e = t; e < 1920; e += 256) dB[e] = bHi[e];
    __syncthreads();
    MMA_PASS();
    __syncthreads();
    #pragma unroll
    for (int e = t; e < 1920; e += 256) dA[e] = aLo[e];
    __syncthreads();
    MMA_PASS();

    int lh = g_len[1][b], lp = g_len[0][b];
    int lhl = min(max(lh - jh*128, 0), 128);
    int lpl = min(max(lp - ih*128, 0), 128);

    float i1a[4], i1b[4], i2a[4], i2b[4];
    #pragma unroll
    for (int m = 0; m < 4; m++) {
        i1a[m] = inv1s[wi*64 + m*16 + g];
        i1b[m] = inv1s[wi*64 + m*16 + g + 8];
    }
    #pragma unroll
    for (int n = 0; n < 4; n++) {
        i2a[n] = inv2s[wj*32 + n*8 + 2*q];
        i2b[n] = inv2s[wj*32 + n*8 + 2*q + 1];
    }

    float jsum[8], jmaxv[8], isum[8], imaxv[8];
    #pragma unroll
    for (int k = 0; k < 8; k++) { jsum[k] = 0.f; jmaxv[k] = NEGINF; isum[k] = 0.f; imaxv[k] = NEGINF; }

    #pragma unroll
    for (int m = 0; m < 4; m++) {
        int r0v = wi*64 + m*16 + g;
        bool rv0 = r0v < lpl, rv1 = (r0v + 8) < lpl;
        #pragma unroll
        for (int n = 0; n < 4; n++) {
            int c0 = wj*32 + n*8 + 2*q;
            bool cv0 = c0 < lhl, cv1 = (c0 + 1) < lhl;
            float v0 = acc[m][n][0]*i1a[m]*i2a[n];
            float v1 = acc[m][n][1]*i1a[m]*i2b[n];
            float v2 = acc[m][n][2]*i1b[m]*i2a[n];
            float v3 = acc[m][n][3]*i1b[m]*i2b[n];
            jsum[2*m] += v0 + v1;  jsum[2*m+1] += v2 + v3;
            if (cv0) { jmaxv[2*m] = fmaxf(jmaxv[2*m], v0); jmaxv[2*m+1] = fmaxf(jmaxv[2*m+1], v2); }
            if (cv1) { jmaxv[2*m] = fmaxf(jmaxv[2*m], v1); jmaxv[2*m+1] = fmaxf(jmaxv[2*m+1], v3); }
            isum[2*n] += v0 + v2;  isum[2*n+1] += v1 + v3;
            if (rv0) { imaxv[2*n] = fmaxf(imaxv[2*n], v0); imaxv[2*n+1] = fmaxf(imaxv[2*n+1], v1); }
            if (rv1) { imaxv[2*n] = fmaxf(imaxv[2*n], v2); imaxv[2*n+1] = fmaxf(imaxv[2*n+1], v3); }
            if (p == PP) {
                float* dst = g_cos + (size_t)(b*SS + ih*128 + r0v)*SS + jh*128 + c0;
                float2 s0; s0.x = v0; s0.y = v1;
                float2 s1; s1.x = v2; s1.y = v3;
                *(float2*)dst = s0;
                *(float2*)(dst + 8*SS) = s1;
            }
        }
    }

    #pragma unroll
    for (int k = 0; k < 8; k++) {
        #pragma unroll
        for (int off = 1; off <= 2; off <<= 1) {
            jsum[k] += __shfl_xor_sync(0xffffffffu, jsum[k], off);
            jmaxv[k] = fmaxf(jmaxv[k], __shfl_xor_sync(0xffffffffu, jmaxv[k], off));
        }
        #pragma unroll
        for (int off = 4; off <= 16; off <<= 1) {
            isum[k] += __shfl_xor_sync(0xffffffffu, isum[k], off);
            imaxv[k] = fmaxf(imaxv[k], __shfl_xor_sync(0xffffffffu, imaxv[k], off));
        }
    }
    if (q == 0) {
        #pragma unroll
        for (int m = 0; m < 4; m++) {
            #pragma unroll
            for (int hf = 0; hf < 2; hf++) {
                int row = wi*64 + m*16 + hf*8 + g;
                sjred[wj*128 + row] = jsum[2*m + hf];
                mjred[wj*128 + row] = jmaxv[2*m + hf];
            }
        }
    }
    if (g == 0) {
        #pragma unroll
        for (int n = 0; n < 4; n++) {
            int c0 = wj*32 + n*8 + 2*q;
            sired[wi*128 + c0] = isum[2*n];     sired[wi*128 + c0 + 1] = isum[2*n+1];
            mired[wi*128 + c0] = imaxv[2*n];    mired[wi*128 + c0 + 1] = imaxv[2*n+1];
        }
    }
    __syncthreads();
    if (t < 128) {
        float s = sjred[t] + sjred[128 + t] + sjred[256 + t] + sjred[384 + t];
        float m = fmaxf(fmaxf(mjred[t], mjred[128 + t]), fmaxf(mjred[256 + t], mjred[384 + t]));
        int idx = (b*NP + p)*SS + ih*128 + t;
        g_psum[jh][idx] = s;
        g_pmax[jh][idx] = m;
        float s2 = sired[t] + sired[128 + t];
        float m2 = fmaxf(mired[t], mired[128 + t]);
        int idx2 = (b*NP + p)*SS + jh*128 + t;
        g_hsum[ih][idx2] = s2;
        g_hmax[ih][idx2] = m2;
    }
}

// ---- K3: comb + attentive mean/max + all matchings. 8 tokens/block, grid 512 -----
__global__ void __launch_bounds__(256) k_att(const float* __restrict__ w_att,
                                             const float* __restrict__ w_ma,
                                             const float* __restrict__ w_full,
                                             float* __restrict__ out)
{
    __shared__ __align__(16) float buf1[SS*12];  // cst[j][12] (8 used); alias wsqc[20][101]
    __shared__ float red_s[2][8][104], red_m[2][8][104];
    __shared__ float amean[8][104], amax[8][104], lastv[104], rsum[8];
    int b = blockIdx.x, tl = blockIdx.y, side = blockIdx.z;
    int t = threadIdx.x;
    int dlen = side ? g_len[0][b] : g_len[1][b];
    float (*cst)[12] = (float(*)[12])buf1;

    // --- comb (8 tokens x 21 p) ---
    if (t < 168) {
        int il = t / 21, p = t - (t/21)*21;
        int tk = tl*8 + il;
        int idx = (b*NP + p)*SS + tk;
        float sm, mx;
        if (side == 0) {
            sm = g_psum[0][idx] + g_psum[1][idx];
            mx = fmaxf(g_pmax[0][idx], g_pmax[1][idx]);
        } else {
            sm = g_hsum[0][idx] + g_hsum[1][idx];
            mx = fmaxf(g_hmax[0][idx], g_hmax[1][idx]);
        }
        float* oo = out + ((size_t)side*NTOK + b*SS + tk)*OD;
        if (p < PP) { oo[23 + p] = mx; oo[43 + p] = sm / (float)dlen; }
        else        { oo[0] = mx;      oo[1] = sm / (float)dlen; rsum[il] = sm; }
    }
    if (t < 104) lastv[t] = (t < HH) ? g_last[side ^ 1][b*HH + t] : 0.f;

    // --- cos tile load, transposed cst[reduce_idx][il], stride 12 ---
    if (side == 0) {
        for (int e = t; e < 8*SS; e += 256) {
            int j = e >> 3, il = e & 7;
            cst[j][il] = g_cos[(b*SS + tl*8 + il)*SS + j];
        }
    } else {
        for (int e = t; e < 8*SS; e += 256) {
            int i = e >> 3, il = e & 7;
            cst[i][il] = g_cos[(b*SS + i)*SS + tl*8 + il];
        }
    }
    __syncthreads();

    // --- attentive mean + max over reduce dim (float4 broadcast loads) ---
    int g2 = t >> 7, h = t & 127;
    const float* vec = side ? g_cp : g_ch;
    int jbeg = g2*128, jend = min(dlen, jbeg + 128);
    float sm8[8], mx8[8];
    #pragma unroll
    for (int il = 0; il < 8; il++) { sm8[il] = 0.f; mx8[il] = NEGINF; }
    if (h < HH) {
        for (int j = jbeg; j < jend; j++) {
            float c = __ldg(&vec[(b*SS + j)*HH + h]);
            float4 ca = *(const float4*)&cst[j][0];
            float4 cb = *(const float4*)&cst[j][4];
            float f0 = ca.x*c, f1 = ca.y*c, f2 = ca.z*c, f3 = ca.w*c;
            float f4 = cb.x*c, f5 = cb.y*c, f6 = cb.z*c, f7 = cb.w*c;
            sm8[0] += f0; sm8[1] += f1; sm8[2] += f2; sm8[3] += f3;
            sm8[4] += f4; sm8[5] += f5; sm8[6] += f6; sm8[7] += f7;
            mx8[0] = fmaxf(mx8[0], f0); mx8[1] = fmaxf(mx8[1], f1);
            mx8[2] = fmaxf(mx8[2], f2); mx8[3] = fmaxf(mx8[3], f3);
            mx8[4] = fmaxf(mx8[4], f4); mx8[5] = fmaxf(mx8[5], f5);
            mx8[6] = fmaxf(mx8[6], f6); mx8[7] = fmaxf(mx8[7], f7);
        }
        #pragma unroll
        for (int il = 0; il < 8; il++) { red_s[g2][il][h] = sm8[il]; red_m[g2][il][h] = mx8[il]; }
    }
    __syncthreads();
    if (g2 == 0 && h < HH) {
        #pragma unroll
        for (int il = 0; il < 8; il++) {
            float s = red_s[0][il][h] + red_s[1][il][h];
            float m = fmaxf(red_m[0][il][h], red_m[1][il][h]);
            amean[il][h] = s / fmaxf(rsum[il], EPSF);
            amax[il][h] = m;
        }
    }

    // --- match phase: warp wl = token tl*8+wl; which: 0=att, 1=maxatt, 2=full ---
    int wl = t >> 5, lane = t & 31;
    int tok = b*SS + tl*8 + wl;
    const float* v1g = (side ? g_ch : g_cp) + (size_t)tok*HH;
    float* o = out + ((size_t)side*NTOK + tok)*OD;
    float* wsqc = buf1;                  // [20][101], aliases cst after sync
    float* prod1 = &red_s[0][wl][0];
    float* prod2 = &red_s[1][wl][0];

    float r1[4];
    float q1 = 0.f;
    #pragma unroll
    for (int k = 0; k < 4; k++) {
        int hh = k*32 + lane;
        r1[k] = (hh < HH) ? v1g[hh] : 0.f;
        q1 += r1[k]*r1[k];
    }
    #pragma unroll
    for (int of = 16; of; of >>= 1) q1 += __shfl_xor_sync(0xffffffffu, q1, of);

    const float* wlist[3] = {w_att, w_ma, w_full};
    #pragma unroll 1
    for (int which = 0; which < 3; which++) {
        __syncthreads();
        const float* wsrc = wlist[which];
        for (int e = t; e < 2020; e += 256) {
            int p = e / 101, hh = e - p*101;
            float wv = (hh < HH) ? wsrc[p*HH + hh] : 0.f;
            wsqc[e] = wv*wv;
        }
        __syncthreads();

        const float* v2s = (which == 0) ? &amean[wl][0] : (which == 1) ? &amax[wl][0] : lastv;
        const float* wn1 = g_wn[side][(which == 2) ? 0 : (2 + which)];
        int col = (which == 0) ? 63 : (which == 1) ? 84 : 2;

        float r2[4];
        float d = 0.f, q2 = 0.f;
        #pragma unroll
        for (int k = 0; k < 4; k++) {
            int hh = k*32 + lane;
            float c = (hh < HH) ? v2s[hh] : 0.f;
            r2[k] = c;
            d += r1[k]*c; q2 += c*c;
        }
        #pragma unroll
        for (int of = 16; of; of >>= 1) {
            d  += __shfl_xor_sync(0xffffffffu, d, of);
            q2 += __shfl_xor_sync(0xffffffffu, q2, of);
        }
        if (lane == 0)
            o[col] = d / (fmaxf(sqrtf(q1), EPSF) * fmaxf(sqrtf(q2), EPSF));

        #pragma unroll
        for (int k = 0; k < 4; k++) {
            int hh = k*32 + lane;
            if (hh < HH) { prod1[hh] = r1[k]*r2[k]; prod2[hh] = r2[k]*r2[k]; }
        }
        __syncwarp();
        if (lane < PP) {
            float s12 = 0.f, s22 = 0.f;
            const float* wr = wsqc + lane*101;
            #pragma unroll 4
            for (int hh = 0; hh < HH; hh++) {
                float wq = wr[hh];
                s12 += wq * prod1[hh];
                s22 += wq * prod2[hh];
            }
            float n1 = wn1[tok*PP + lane];
            o[col + 1 + lane] = s12 / (fmaxf(n1, EPSF) * fmaxf(sqrtf(s22), EPSF));
        }
        __syncwarp();
    }
}

// ---- launcher ----------------------------------------------------------------------
extern "C" void kernel_launch(void* const* d_in, const int* in_sizes, int n_in,
                              void* d_out, int out_size)
{
    const float* ctx_p  = (const float*)d_in[0];
    const int*   mask_p = (const int*)  d_in[1];
    const float* ctx_h  = (const float*)d_in[2];
    const int*   mask_h = (const int*)  d_in[3];
    const float* w_full = (const float*)d_in[4];
    const float* w_mp   = (const float*)d_in[5];
    const float* w_att  = (const float*)d_in[6];
    const float* w_ma   = (const float*)d_in[7];
    float* out = (float*)d_out;

    cudaFuncSetAttribute(k_mma, cudaFuncAttributeMaxDynamicSharedMemorySize, SMEM_DYN);

    k_prep<<<dim3(8, BB, 2), 256>>>(ctx_p, mask_p, ctx_h, mask_h, w_full, w_mp, w_att, w_ma);
    k_splitA<<<dim3(2, NP, BB), 256>>>(w_mp);
    k_mma<<<dim3(4, NP, BB), 256, SMEM_DYN>>>();
    k_att<<<dim3(BB, 32, 2), 256>>>(w_att, w_ma, w_full, out);
}